// round 2
// baseline (speedup 1.0000x reference)
#include <cuda_runtime.h>
#include <cuda_bf16.h>
#include <cstdint>

// Problem constants
#define NN 2048
#define NROWS 16384
#define ROWS_PER_BLOCK 8
#define THREADS 256
#define CHUNK 64
// padded layout: p(k) = k + (k>>6); row stride = 2048 + 32 = 2080 words
#define PADSTRIDE 2080

__device__ float g_cs[NN];
__device__ float g_sn[NN];

// Tiny kernel: precompute cos/sin of angles
__global__ void rg_sincos_kernel(const float* __restrict__ angles) {
    int k = blockIdx.x * blockDim.x + threadIdx.x;
    if (k < NN) {
        float s, c;
        sincosf(angles[k], &s, &c);
        g_cs[k] = c;
        g_sn[k] = s;
    }
}

// Main kernel: warp-per-row chunked affine-scan Givens application.
// y = x @ R.T applied as 2048 sequential Givens rotations per row,
// parallelized exactly via affine-map composition across 32 lane-chunks.
__global__ __launch_bounds__(THREADS, 2)
void rg_givens_kernel(const float* __restrict__ x, float* __restrict__ y) {
    extern __shared__ float sm[];
    float* xs   = sm;                                   // [ROWS_PER_BLOCK][PADSTRIDE]
    float* cs_s = sm + ROWS_PER_BLOCK * PADSTRIDE;      // [PADSTRIDE]
    float* sn_s = cs_s + PADSTRIDE;                     // [PADSTRIDE]

    const int tid  = threadIdx.x;
    const int lane = tid & 31;
    const int w    = tid >> 5;                          // warp id = row within block
    const int row  = blockIdx.x * ROWS_PER_BLOCK + w;
    float* xrow_s = xs + w * PADSTRIDE;

    // Cooperative load of cos/sin into padded smem (block-wide)
    for (int k = tid; k < NN; k += THREADS) {
        int p = k + (k >> 6);
        cs_s[p] = g_cs[k];
        sn_s[p] = g_sn[k];
    }

    // Each warp loads its row: coalesced float4 LDG, scalar STS into padded layout
    const float4* xrow = (const float4*)(x + (size_t)row * NN);
    #pragma unroll
    for (int i = 0; i < (NN / 4) / 32; i++) {
        int v4 = i * 32 + lane;
        float4 val = xrow[v4];
        int k = v4 * 4;
        int p = k + (k >> 6);   // k%64 <= 60 so all 4 words share the pad block
        xrow_s[p + 0] = val.x;
        xrow_s[p + 1] = val.y;
        xrow_s[p + 2] = val.z;
        xrow_s[p + 3] = val.w;
    }
    __syncthreads();  // cs/sn ready block-wide; x ready per-warp

    // w0 = s_{2047}*x_{2047} + c_{2047}*x_0  (this becomes x~_0)
    const int pTop = 2047 + (2047 >> 6);
    float x0    = xrow_s[0];
    float x2047 = xrow_s[pTop];
    float w0 = fmaf(sn_s[pTop], x2047, cs_s[pTop] * x0);
    __syncwarp();
    if (lane == 0) xrow_s[0] = w0;
    __syncwarp();

    // ---- Stage 2: per-lane chunk affine map (A, B): carry_out = A + B*carry_in ----
    // chunk k-range: [64*lane, 64*lane+63], processed descending.
    const int pbase = 65 * lane;   // padded base = 64*lane + lane
    float A = 0.0f, Bm = 1.0f;
    #pragma unroll 4
    for (int t = CHUNK - 1; t >= 0; t--) {
        int p = pbase + t;
        float xv = xrow_s[p];
        float a  = cs_s[p] * xv;
        float b  = -sn_s[p];
        A  = fmaf(b, A, a);
        Bm = Bm * b;
    }

    // ---- Suffix scan of affine maps: g_c = f_c ∘ f_{c+1} ∘ ... ∘ f_31 ----
    float gA = A, gB = Bm;
    #pragma unroll
    for (int d = 1; d < 32; d <<= 1) {
        float A2 = __shfl_down_sync(0xffffffffu, gA, d);
        float B2 = __shfl_down_sync(0xffffffffu, gB, d);
        if (lane + d < 32) {
            gA = fmaf(gB, A2, gA);   // (self) ∘ (next): A + B*A2, B*B2
            gB = gB * B2;
        }
    }
    // carry entering chunk c = g_{c+1}(x0); top chunk gets x0 itself.
    float nA = __shfl_down_sync(0xffffffffu, gA, 1);
    float nB = __shfl_down_sync(0xffffffffu, gB, 1);
    float carry = (lane == 31) ? x0 : fmaf(nB, x0, nA);

    // Pre-read contested boundary element (written first by lane-1, read last by us)
    float xlo = xrow_s[pbase];
    __syncwarp();

    // ---- Stage 3: replay with true carry; write y in place into xs ----
    const int base = lane * CHUNK;
    #pragma unroll 4
    for (int t = CHUNK - 1; t >= 0; t--) {
        int p = pbase + t;
        float xv = (t == 0) ? xlo : xrow_s[p];
        float c = cs_s[p];
        float s = sn_s[p];
        float out = fmaf(s, xv, c * carry);
        carry     = fmaf(c, xv, -s * carry);
        int k = base + t;
        if (k != 2047) {
            int kp1 = k + 1;
            xrow_s[kp1 + (kp1 >> 6)] = out;   // y[k+1]
        }
    }
    if (lane == 0) xrow_s[0] = carry;          // y[0]
    __syncwarp();

    // ---- Store row: padded smem -> coalesced float4 STG ----
    float4* yrow = (float4*)(y + (size_t)row * NN);
    #pragma unroll
    for (int i = 0; i < (NN / 4) / 32; i++) {
        int v4 = i * 32 + lane;
        int k = v4 * 4;
        int p = k + (k >> 6);
        float4 val;
        val.x = xrow_s[p + 0];
        val.y = xrow_s[p + 1];
        val.z = xrow_s[p + 2];
        val.w = xrow_s[p + 3];
        yrow[v4] = val;
    }
}

extern "C" void kernel_launch(void* const* d_in, const int* in_sizes, int n_in,
                              void* d_out, int out_size) {
    const float* x      = (const float*)d_in[0];   // [16384, 2048] fp32
    const float* angles = (const float*)d_in[1];   // [2048] fp32
    float* y = (float*)d_out;                      // [16384, 2048] fp32

    (void)in_sizes; (void)n_in; (void)out_size;

    rg_sincos_kernel<<<(NN + 255) / 256, 256>>>(angles);

    const int smem_bytes = (ROWS_PER_BLOCK * PADSTRIDE + 2 * PADSTRIDE) * sizeof(float);
    static bool attr_set = false;
    if (!attr_set) {
        cudaFuncSetAttribute(rg_givens_kernel,
                             cudaFuncAttributeMaxDynamicSharedMemorySize, smem_bytes);
        attr_set = true;
    }
    rg_givens_kernel<<<NROWS / ROWS_PER_BLOCK, THREADS, smem_bytes>>>(x, y);
}

// round 3
// speedup vs baseline: 1.2007x; 1.2007x over previous
#include <cuda_runtime.h>
#include <cuda_bf16.h>
#include <cstdint>

// Problem constants
#define NN 2048
#define NROWS 16384
#define ROWS_PER_BLOCK 8
#define THREADS 512          // 16 warps: 2 warps per row
#define CHUNK 32             // elements per lane
// padded layout: p(k) = k + (k>>5); row stride = 2048 + 64 = 2112 words
#define PADSTRIDE 2112
#define PTOP 2110            // p(2047) = 2047 + 63

__device__ float2 g_csn[NN];

// Tiny kernel: precompute cos/sin of angles, packed as float2
__global__ void rg_sincos_kernel(const float* __restrict__ angles) {
    int k = blockIdx.x * blockDim.x + threadIdx.x;
    if (k < NN) {
        float s, c;
        sincosf(angles[k], &s, &c);
        g_csn[k] = make_float2(c, s);
    }
}

// Main kernel: 2 warps per row, chunked affine-scan Givens application.
__global__ __launch_bounds__(THREADS, 2)
void rg_givens_kernel(const float* __restrict__ x, float* __restrict__ y) {
    extern __shared__ float sm[];
    float*  xs    = sm;                                     // [8][PADSTRIDE]
    float2* csn_s = (float2*)(sm + ROWS_PER_BLOCK * PADSTRIDE); // [PADSTRIDE]
    float*  comm  = (float*)(csn_s + PADSTRIDE);            // [ROWS_PER_BLOCK]

    const int tid  = threadIdx.x;
    const int lane = tid & 31;
    const int w    = tid >> 5;
    const int rib  = w >> 1;          // row in block
    const int h    = w & 1;           // half of row (0 = low k, 1 = high k)
    const int row  = blockIdx.x * ROWS_PER_BLOCK + rib;
    float* xr = xs + rib * PADSTRIDE;

    // ---- Load: each warp loads its half-row, coalesced float4 ----
    const float4* xrow = (const float4*)(x + (size_t)row * NN);
    #pragma unroll
    for (int i = 0; i < 8; i++) {
        int v4 = h * 256 + i * 32 + lane;
        float4 val = xrow[v4];
        int k = v4 * 4;
        int p = k + (k >> 5);          // 4 words stay within one 32-block
        xr[p + 0] = val.x;
        xr[p + 1] = val.y;
        xr[p + 2] = val.z;
        xr[p + 3] = val.w;
    }
    // cos/sin block-wide into padded smem (one LDG.64 + STS.64 each)
    #pragma unroll
    for (int k = tid; k < NN; k += THREADS) {
        csn_s[k + (k >> 5)] = g_csn[k];
    }
    __syncthreads();

    // x0 (original) needed by everyone as the chain's initial carry
    const float x0 = xr[0];
    // w0 = s_top * x_2047 + c_top * x_0  (becomes x~_0, used only by lane C==0)
    float w0 = 0.0f;
    if (h == 0) {
        float xT = xr[PTOP];
        float2 ct = csn_s[PTOP];
        w0 = fmaf(ct.y, xT, ct.x * x0);
    }

    const int C = h * 32 + lane;       // global chunk id 0..63
    const int pbase = 33 * C;          // p(32*C)

    // Pre-read boundary element (raced in stage 3); substitute w0 at C==0.
    const float xlo = (C == 0) ? w0 : xr[pbase];

    // ---- Stage 2: per-lane chunk affine map: carry_out = A + Bm*carry_in ----
    float A = 0.0f, Bm = 1.0f;
    #pragma unroll 4
    for (int t = CHUNK - 1; t >= 1; t--) {
        int p = pbase + t;
        float xv = xr[p];
        float2 cs = csn_s[p];
        float a = cs.x * xv;
        A  = fmaf(-cs.y, A, a);
        Bm = -cs.y * Bm;
    }
    { // peeled t = 0 (uses xlo / w0)
        float2 cs = csn_s[pbase];
        float a = cs.x * xlo;
        A  = fmaf(-cs.y, A, a);
        Bm = -cs.y * Bm;
    }

    // ---- Suffix scan of affine maps within each warp ----
    float gA = A, gB = Bm;
    #pragma unroll
    for (int d = 1; d < 32; d <<= 1) {
        float A2 = __shfl_down_sync(0xffffffffu, gA, d);
        float B2 = __shfl_down_sync(0xffffffffu, gB, d);
        if (lane + d < 32) {
            gA = fmaf(gB, A2, gA);
            gB = gB * B2;
        }
    }
    float nA = __shfl_down_sync(0xffffffffu, gA, 1);
    float nB = __shfl_down_sync(0xffffffffu, gB, 1);

    // Warp1 (high half) enters with x0; its total map output feeds warp0.
    if (h == 1 && lane == 0) {
        comm[rib] = fmaf(gB, x0, gA);
    }
    __syncthreads();

    float cin = (h == 0) ? comm[rib] : x0;
    float carry = (lane == 31) ? cin : fmaf(nB, cin, nA);

    // ---- Stage 3: replay with true carry; write y into xs ----
    const int kbase = C * CHUNK;
    #pragma unroll 4
    for (int t = CHUNK - 1; t >= 1; t--) {
        int p = pbase + t;
        float xv = xr[p];
        float2 cs = csn_s[p];
        float t1 = cs.y * xv;          // s*x   (independent of carry)
        float t2 = cs.x * xv;          // c*x   (independent of carry)
        float out = fmaf(cs.x, carry, t1);
        carry = fmaf(-cs.y, carry, t2);   // 4-cycle chain
        int k = kbase + t;
        if (k != 2047) {
            int k1 = k + 1;
            xr[k1 + (k1 >> 5)] = out;  // y[k+1]
        }
    }
    { // peeled t = 0
        float2 cs = csn_s[pbase];
        float t1 = cs.y * xlo;
        float t2 = cs.x * xlo;
        float out = fmaf(cs.x, carry, t1);
        carry = fmaf(-cs.y, carry, t2);
        int k1 = kbase + 1;            // kbase <= 2016, never 2047
        xr[k1 + (k1 >> 5)] = out;
    }
    if (C == 0) xr[0] = carry;         // y[0] = final chain carry
    __syncthreads();

    // ---- Store: padded smem -> coalesced float4 ----
    float4* yrow = (float4*)(y + (size_t)row * NN);
    #pragma unroll
    for (int i = 0; i < 8; i++) {
        int v4 = h * 256 + i * 32 + lane;
        int k = v4 * 4;
        int p = k + (k >> 5);
        float4 val;
        val.x = xr[p + 0];
        val.y = xr[p + 1];
        val.z = xr[p + 2];
        val.w = xr[p + 3];
        yrow[v4] = val;
    }
}

extern "C" void kernel_launch(void* const* d_in, const int* in_sizes, int n_in,
                              void* d_out, int out_size) {
    const float* x      = (const float*)d_in[0];   // [16384, 2048] fp32
    const float* angles = (const float*)d_in[1];   // [2048] fp32
    float* y = (float*)d_out;                      // [16384, 2048] fp32

    (void)in_sizes; (void)n_in; (void)out_size;

    rg_sincos_kernel<<<(NN + 255) / 256, 256>>>(angles);

    const int smem_bytes = (ROWS_PER_BLOCK * PADSTRIDE) * sizeof(float)
                         + PADSTRIDE * sizeof(float2)
                         + ROWS_PER_BLOCK * sizeof(float);
    static bool attr_set = false;
    if (!attr_set) {
        cudaFuncSetAttribute(rg_givens_kernel,
                             cudaFuncAttributeMaxDynamicSharedMemorySize, smem_bytes);
        attr_set = true;
    }
    rg_givens_kernel<<<NROWS / ROWS_PER_BLOCK, THREADS, smem_bytes>>>(x, y);
}

// round 4
// speedup vs baseline: 1.3231x; 1.1020x over previous
#include <cuda_runtime.h>
#include <cuda_bf16.h>
#include <cstdint>

// Problem constants
#define NN 2048
#define NROWS 16384
#define ROWS_PER_BLOCK 4
#define THREADS 512          // 16 warps: 4 warps per row
#define CHUNK 16             // elements per lane
// padded layout: p(k) = k + (k>>5); row stride = 2048 + 64 = 2112 words
#define PADSTRIDE 2112
#define PTOP 2110            // p(2047)

__device__ float2 g_csn[NN];

__global__ void rg_sincos_kernel(const float* __restrict__ angles) {
    int k = blockIdx.x * blockDim.x + threadIdx.x;
    if (k < NN) {
        float s, c;
        sincosf(angles[k], &s, &c);
        g_csn[k] = make_float2(c, s);
    }
}

// 4 warps per row, chunk-16 affine-scan Givens application, x held in registers.
__global__ __launch_bounds__(THREADS, 2)
void rg_givens_kernel(const float* __restrict__ x, float* __restrict__ y) {
    extern __shared__ float sm[];
    float* xs  = sm;                                   // [4][PADSTRIDE]
    float* c_s = sm + ROWS_PER_BLOCK * PADSTRIDE;      // [PADSTRIDE]
    float* s_s = c_s + PADSTRIDE;                      // [PADSTRIDE]
    float* wmA = s_s + PADSTRIDE;                      // [4 rows][4 warps]
    float* wmB = wmA + 16;                             // [4 rows][4 warps]

    const int tid  = threadIdx.x;
    const int lane = tid & 31;
    const int w    = tid >> 5;
    const int rib  = w >> 2;          // row in block
    const int h    = w & 3;           // quarter of row
    const int row  = blockIdx.x * ROWS_PER_BLOCK + rib;
    float* xr = xs + rib * PADSTRIDE;

    // ---- Stage 1: staging ----
    // x: each warp loads its quarter-row, coalesced float4 LDG + scalar STS (conflict-free)
    const float4* xrow = (const float4*)(x + (size_t)row * NN);
    #pragma unroll
    for (int i = 0; i < 4; i++) {
        int v4 = h * 128 + i * 32 + lane;
        float4 val = xrow[v4];
        int k = v4 * 4;
        int p = k + (k >> 5);
        xr[p + 0] = val.x;
        xr[p + 1] = val.y;
        xr[p + 2] = val.z;
        xr[p + 3] = val.w;
    }
    // cos/sin into separate padded arrays (block-wide)
    #pragma unroll
    for (int k = tid; k < NN; k += THREADS) {
        float2 v = g_csn[k];
        int p = k + (k >> 5);
        c_s[p] = v.x;
        s_s[p] = v.y;
    }
    __syncthreads();

    const float x0 = xr[0];
    // w0 = s_top*x_2047 + c_top*x_0  (replaces x~_0); computed by warp h==0
    float w0 = 0.0f;
    if (h == 0) {
        float xT = xr[PTOP];
        w0 = fmaf(s_s[PTOP], xT, c_s[PTOP] * x0);
    }

    const int C = h * 32 + lane;       // global chunk id 0..127
    const int pbase = 16 * C + (C >> 1);

    // ---- Load chunk x into registers (conflict-free scalar LDS) ----
    float xv[CHUNK];
    #pragma unroll
    for (int t = 0; t < CHUNK; t++) xv[t] = xr[pbase + t];
    if (C == 0) xv[0] = w0;

    // ---- Stage 2: chunk affine map: carry_out = A + Bm*carry_in ----
    float A = 0.0f, Bm = 1.0f;
    #pragma unroll
    for (int t = CHUNK - 1; t >= 0; t--) {
        float lc = c_s[pbase + t];
        float ls = s_s[pbase + t];
        A  = fmaf(-ls, A, lc * xv[t]);
        Bm = -ls * Bm;
    }

    // ---- Warp suffix scan of affine maps ----
    float gA = A, gB = Bm;
    #pragma unroll
    for (int d = 1; d < 32; d <<= 1) {
        float A2 = __shfl_down_sync(0xffffffffu, gA, d);
        float B2 = __shfl_down_sync(0xffffffffu, gB, d);
        if (lane + d < 32) {
            gA = fmaf(gB, A2, gA);
            gB = gB * B2;
        }
    }
    float nA = __shfl_down_sync(0xffffffffu, gA, 1);
    float nB = __shfl_down_sync(0xffffffffu, gB, 1);

    // lane 0 of each warp holds the warp's full map; publish it
    if (lane == 0) {
        wmA[rib * 4 + h] = gA;
        wmB[rib * 4 + h] = gB;
    }
    __syncthreads();

    // entering carry for this warp = (W_{h+1} o ... o W_3)(x0)
    float cin = x0;
    #pragma unroll
    for (int j = 3; j >= 1; j--) {
        if (j > h) cin = fmaf(wmB[rib * 4 + j], cin, wmA[rib * 4 + j]);
    }
    float carry = (lane == 31) ? cin : fmaf(nB, cin, nA);

    // ---- Stage 3: replay with true carry; write y into xs ----
    const int pnext = 16 * (C + 1) + ((C + 1) >> 1);   // p(16*(C+1)) for the t=15 write
    #pragma unroll
    for (int t = CHUNK - 1; t >= 0; t--) {
        float lc = c_s[pbase + t];
        float ls = s_s[pbase + t];
        float out = fmaf(lc, carry, ls * xv[t]);
        carry = fmaf(-ls, carry, lc * xv[t]);
        if (t == CHUNK - 1) {
            if (C != 127) xr[pnext] = out;     // y[16(C+1)]
        } else {
            xr[pbase + t + 1] = out;           // y[16C + t + 1]
        }
    }
    if (C == 0) xr[0] = carry;                 // y[0]
    __syncthreads();

    // ---- Store: padded smem -> coalesced float4 ----
    float4* yrow = (float4*)(y + (size_t)row * NN);
    #pragma unroll
    for (int i = 0; i < 4; i++) {
        int v4 = h * 128 + i * 32 + lane;
        int k = v4 * 4;
        int p = k + (k >> 5);
        float4 val;
        val.x = xr[p + 0];
        val.y = xr[p + 1];
        val.z = xr[p + 2];
        val.w = xr[p + 3];
        yrow[v4] = val;
    }
}

extern "C" void kernel_launch(void* const* d_in, const int* in_sizes, int n_in,
                              void* d_out, int out_size) {
    const float* x      = (const float*)d_in[0];   // [16384, 2048] fp32
    const float* angles = (const float*)d_in[1];   // [2048] fp32
    float* y = (float*)d_out;                      // [16384, 2048] fp32

    (void)in_sizes; (void)n_in; (void)out_size;

    rg_sincos_kernel<<<(NN + 255) / 256, 256>>>(angles);

    const int smem_bytes = (ROWS_PER_BLOCK * PADSTRIDE + 2 * PADSTRIDE + 32) * sizeof(float);
    static bool attr_set = false;
    if (!attr_set) {
        cudaFuncSetAttribute(rg_givens_kernel,
                             cudaFuncAttributeMaxDynamicSharedMemorySize, smem_bytes);
        attr_set = true;
    }
    rg_givens_kernel<<<NROWS / ROWS_PER_BLOCK, THREADS, smem_bytes>>>(x, y);
}